// round 8
// baseline (speedup 1.0000x reference)
#include <cuda_runtime.h>
#include <cstdint>

// Problem constants: x (8, 48, 48, 48, 64) fp32
#define B_   8
#define C_   64
#define N_   110592          // 48*48*48
#define NB_  (C_ * N_)       // 7077888 elements per batch

// Scratch (no allocs allowed): Gram and affinity matrices, 8 x 64 x 64 fp32 each
__device__ float g_G[B_ * C_ * C_];
__device__ float g_A[B_ * C_ * C_];

// ---------------------------------------------------------------------------
// warp mma m16n8k8 tf32: D(16x8,f32) += A(16x8,tf32 row) * B(8x8,tf32 col)
// fragment layout (lane = 4*g + tg, g=lane>>2, tg=lane&3):
//   a0=(g,tg) a1=(g+8,tg) a2=(g,tg+4) a3=(g+8,tg+4)
//   b0=(tg,g) b1=(tg+4,g)
//   c0=(g,2tg) c1=(g,2tg+1) c2=(g+8,2tg) c3=(g+8,2tg+1)
// ---------------------------------------------------------------------------
__device__ __forceinline__ void mma_tf32(
    float& d0, float& d1, float& d2, float& d3,
    uint32_t a0, uint32_t a1, uint32_t a2, uint32_t a3,
    uint32_t b0, uint32_t b1)
{
    asm volatile(
        "mma.sync.aligned.m16n8k8.row.col.f32.tf32.tf32.f32 "
        "{%0,%1,%2,%3}, {%4,%5,%6,%7}, {%8,%9}, {%0,%1,%2,%3};\n"
        : "+f"(d0), "+f"(d1), "+f"(d2), "+f"(d3)
        : "r"(a0), "r"(a1), "r"(a2), "r"(a3), "r"(b0), "r"(b1));
}

__device__ __forceinline__ uint32_t f2u(float f) { return __float_as_uint(f); }

__device__ __forceinline__ uint32_t smem_u32(const void* p) {
    return (uint32_t)__cvta_generic_to_shared(p);
}
__device__ __forceinline__ void cp_async16(uint32_t saddr, const void* gptr) {
    asm volatile("cp.async.ca.shared.global [%0], [%1], 16;\n"
                 :: "r"(saddr), "l"(gptr));
}
__device__ __forceinline__ void cp_commit() {
    asm volatile("cp.async.commit_group;\n");
}
template <int N>
__device__ __forceinline__ void cp_wait() {
    asm volatile("cp.async.wait_group %0;\n" :: "n"(N));
}

// ---------------------------------------------------------------------------
// Kernel 0: zero the Gram accumulator
// ---------------------------------------------------------------------------
__global__ void zeroG_kernel() {
    int i = blockIdx.x * blockDim.x + threadIdx.x;
    if (i < B_ * C_ * C_) g_G[i] = 0.0f;
}

// ---------------------------------------------------------------------------
// Kernel 1: G[b] += K[b] * K[b]^T   (partial Gram per CTA, REDG merge)
// grid (72, 8), block 256, 4 CTAs/SM. Each CTA: 24 chunks of 64 columns,
// 3-stage cp.async pipeline, ONE __syncthreads per chunk:
//   wait<1> ; sync ; prefetch(ch+2) ; commit ; compute(ch)
// The prefetch target buffer (ch+2)%3 == (ch-1)%3 was read in compute(ch-1),
// which every warp finished before this barrier -> safe with a single sync.
// smem: 3 x [64][68] fp32 (68 == 4 mod 32 -> frag reads conflict-free).
// ---------------------------------------------------------------------------
#define S1 68
#define G_CHUNKS 24
__global__ __launch_bounds__(256, 4)
void gram_kernel(const float* __restrict__ x)
{
    extern __shared__ float Ks[];   // 3 * 64 * 68 floats = 52224 B

    const int b    = blockIdx.y;
    const int tid  = threadIdx.x;
    const int warp = tid >> 5;
    const int lane = tid & 31;
    const int g    = lane >> 2;
    const int tg   = lane & 3;
    const int c0   = (warp >> 1) * 16;   // c-block (16 rows)
    const int d0b  = (warp & 1) * 32;    // d-half (32 cols)

    const float* xb   = x + (size_t)b * NB_;
    const int   nbase = blockIdx.x * (G_CHUNKS * 64);

    // per-thread load slots: 4 float4 per 64x64 tile (16 float4 per row)
    const int lrow = tid >> 4;           // rows tid/16, +16, +32, +48
    const int lc4  = (tid & 15) << 2;

    float acc[4][4];
#pragma unroll
    for (int i = 0; i < 4; i++)
#pragma unroll
        for (int j = 0; j < 4; j++) acc[i][j] = 0.0f;

    // prologue: prefetch chunks 0 and 1 (groups 0 and 1)
#pragma unroll
    for (int pf = 0; pf < 2; pf++) {
        const float* gsrc = xb + nbase + pf * 64;
        float* buf = Ks + pf * (64 * S1);
#pragma unroll
        for (int it = 0; it < 4; it++) {
            int row = lrow + it * 16;
            cp_async16(smem_u32(&buf[row * S1 + lc4]),
                       gsrc + (size_t)row * N_ + lc4);
        }
        cp_commit();
    }

    for (int ch = 0; ch < G_CHUNKS; ch++) {
        cp_wait<1>();          // group ch complete -> tile ch resident
        __syncthreads();

        if (ch + 2 < G_CHUNKS) {
            const float* gsrc = xb + nbase + (ch + 2) * 64;
            float* buf = Ks + ((ch + 2) % 3) * (64 * S1);
#pragma unroll
            for (int it = 0; it < 4; it++) {
                int row = lrow + it * 16;
                cp_async16(smem_u32(&buf[row * S1 + lc4]),
                           gsrc + (size_t)row * N_ + lc4);
            }
        }
        cp_commit();           // always commit (possibly empty) -> uniform wait

        const float* buf = Ks + (ch % 3) * (64 * S1);
#pragma unroll
        for (int ks = 0; ks < 8; ks++) {
            const int kk = ks * 8;
            uint32_t a0 = f2u(buf[(c0 + g)     * S1 + kk + tg]);
            uint32_t a1 = f2u(buf[(c0 + 8 + g) * S1 + kk + tg]);
            uint32_t a2 = f2u(buf[(c0 + g)     * S1 + kk + tg + 4]);
            uint32_t a3 = f2u(buf[(c0 + 8 + g) * S1 + kk + tg + 4]);
#pragma unroll
            for (int db = 0; db < 4; db++) {
                int dr = d0b + db * 8 + g;
                uint32_t b0 = f2u(buf[dr * S1 + kk + tg]);
                uint32_t b1 = f2u(buf[dr * S1 + kk + tg + 4]);
                mma_tf32(acc[db][0], acc[db][1], acc[db][2], acc[db][3],
                         a0, a1, a2, a3, b0, b1);
            }
        }
    }

    // merge partials: each accumulator value maps to a distinct G entry
    float* Gb = g_G + b * (C_ * C_);
#pragma unroll
    for (int db = 0; db < 4; db++) {
        int d = d0b + db * 8 + tg * 2;
        atomicAdd(&Gb[(c0 + g)     * C_ + d],     acc[db][0]);
        atomicAdd(&Gb[(c0 + g)     * C_ + d + 1], acc[db][1]);
        atomicAdd(&Gb[(c0 + 8 + g) * C_ + d],     acc[db][2]);
        atomicAdd(&Gb[(c0 + 8 + g) * C_ + d + 1], acc[db][3]);
    }
}

// ---------------------------------------------------------------------------
// Kernel 2: A[b] = sigmoid(G[b] * G[b])   grid(8), block 256
// ---------------------------------------------------------------------------
__global__ __launch_bounds__(256)
void m3_sigmoid_kernel()
{
    __shared__ float Gs[C_ * C_];
    const int b = blockIdx.x;
    for (int i = threadIdx.x; i < C_ * C_; i += 256)
        Gs[i] = g_G[b * C_ * C_ + i];
    __syncthreads();
    for (int i = threadIdx.x; i < C_ * C_; i += 256) {
        int c = i >> 6, d = i & 63;
        float s = 0.0f;
#pragma unroll 8
        for (int k = 0; k < C_; k++)
            s = fmaf(Gs[c * C_ + k], Gs[k * C_ + d], s);
        g_A[b * C_ * C_ + i] = 1.0f / (1.0f + __expf(-s));
    }
}

// ---------------------------------------------------------------------------
// Kernel 3: out = x + gamma * (A[b] @ K[b])
// grid (54, 8), block 256, 3 CTAs/SM. Each CTA: 32 tiles of 64 columns,
// 4-stage cp.async pipeline, ONE __syncthreads per tile (same proof as gram:
// prefetch target (t+4)&3 == (t-1)&3 was consumed in compute(t-1), complete
// for all warps before this barrier). Affinity fragments live in registers.
// smem: 4 x Ks[64][72] (72 == 8 mod 32 -> B-frag (d0+tg)*S + col+g gives
// banks 8tg+g, conflict-free; epilogue LDS.64 conflict-free per phase).
// ---------------------------------------------------------------------------
#define S3 72
#define A_TILES 32
#define A_STAGES 4
__global__ __launch_bounds__(256, 3)
void apply_kernel(const float* __restrict__ x, float* __restrict__ out,
                  const float* __restrict__ gammap)
{
    extern __shared__ float Ks[];        // 4 * 64 * 72 floats = 73728 B

    const int b    = blockIdx.y;
    const int tid  = threadIdx.x;
    const int warp = tid >> 5;
    const int lane = tid & 31;
    const int g    = lane >> 2;
    const int tg   = lane & 3;
    const int c0   = (warp >> 1) * 16;   // c-block (16 rows)
    const int nc0  = (warp & 1) * 32;    // n-half (32 cols)

    const float gamma = gammap[0];
    const float* xb   = x + (size_t)b * NB_;
    float*       ob   = out + (size_t)b * NB_;
    const int   nbase = blockIdx.x * (A_TILES * 64);

    const int lrow = tid >> 4;
    const int lc4  = (tid & 15) << 2;

    // prologue: prefetch tiles 0..2 (groups 0..2)
#pragma unroll
    for (int pf = 0; pf < A_STAGES - 1; pf++) {
        const float* gsrc = xb + nbase + pf * 64;
        float* buf = Ks + pf * (64 * S3);
#pragma unroll
        for (int it = 0; it < 4; it++) {
            int row = lrow + it * 16;
            cp_async16(smem_u32(&buf[row * S3 + lc4]),
                       gsrc + (size_t)row * N_ + lc4);
        }
        cp_commit();
    }

    // hoist affinity fragments: constant across all tiles. 32 regs.
    uint32_t af[8][4];
    {
        const float* Ab = g_A + b * (C_ * C_);
#pragma unroll
        for (int kd = 0; kd < 8; kd++) {
            const int d0 = kd * 8;
            af[kd][0] = f2u(__ldg(&Ab[(c0 + g)     * C_ + d0 + tg]));
            af[kd][1] = f2u(__ldg(&Ab[(c0 + 8 + g) * C_ + d0 + tg]));
            af[kd][2] = f2u(__ldg(&Ab[(c0 + g)     * C_ + d0 + tg + 4]));
            af[kd][3] = f2u(__ldg(&Ab[(c0 + 8 + g) * C_ + d0 + tg + 4]));
        }
    }

    for (int t = 0; t < A_TILES; t++) {
        cp_wait<A_STAGES - 2>();   // group t complete -> tile t resident
        __syncthreads();

        if (t + A_STAGES - 1 < A_TILES) {
            const float* gsrc = xb + nbase + (t + A_STAGES - 1) * 64;
            float* buf = Ks + ((t + A_STAGES - 1) & (A_STAGES - 1)) * (64 * S3);
#pragma unroll
            for (int it = 0; it < 4; it++) {
                int row = lrow + it * 16;
                cp_async16(smem_u32(&buf[row * S3 + lc4]),
                           gsrc + (size_t)row * N_ + lc4);
            }
        }
        cp_commit();               // always commit -> uniform wait count

        const float* buf = Ks + (t & (A_STAGES - 1)) * (64 * S3);

        float acc[4][4];
#pragma unroll
        for (int i = 0; i < 4; i++)
#pragma unroll
            for (int j = 0; j < 4; j++) acc[i][j] = 0.0f;

#pragma unroll
        for (int kd = 0; kd < 8; kd++) {
            const int d0 = kd * 8;
#pragma unroll
            for (int nb = 0; nb < 4; nb++) {
                const int col = nc0 + nb * 8;
                uint32_t b0 = f2u(buf[(d0 + tg)     * S3 + col + g]);
                uint32_t b1 = f2u(buf[(d0 + tg + 4) * S3 + col + g]);
                mma_tf32(acc[nb][0], acc[nb][1], acc[nb][2], acc[nb][3],
                         af[kd][0], af[kd][1], af[kd][2], af[kd][3], b0, b1);
            }
        }

        // epilogue: out = x + gamma * weights (x re-read from smem tile)
        const int n0 = nbase + t * 64;
#pragma unroll
        for (int nb = 0; nb < 4; nb++) {
            const int col = nc0 + nb * 8 + tg * 2;
            const int r0 = c0 + g;
            const int r1 = c0 + 8 + g;
            float2 x0 = *(const float2*)&buf[r0 * S3 + col];
            float2 x1 = *(const float2*)&buf[r1 * S3 + col];
            float2 o0 = make_float2(fmaf(gamma, acc[nb][0], x0.x),
                                    fmaf(gamma, acc[nb][1], x0.y));
            float2 o1 = make_float2(fmaf(gamma, acc[nb][2], x1.x),
                                    fmaf(gamma, acc[nb][3], x1.y));
            *(float2*)(ob + (size_t)r0 * N_ + n0 + col) = o0;
            *(float2*)(ob + (size_t)r1 * N_ + n0 + col) = o1;
        }
    }
}

// ---------------------------------------------------------------------------
// Launch
// ---------------------------------------------------------------------------
extern "C" void kernel_launch(void* const* d_in, const int* in_sizes, int n_in,
                              void* d_out, int out_size)
{
    const float* x     = (const float*)d_in[0];
    const float* gamma = (const float*)d_in[1];
    float*       out   = (float*)d_out;

    (void)in_sizes; (void)n_in; (void)out_size;

    const int smem1 = 3 * 64 * S1 * (int)sizeof(float);          // 52224
    const int smem3 = A_STAGES * 64 * S3 * (int)sizeof(float);   // 73728

    cudaFuncSetAttribute(gram_kernel,
                         cudaFuncAttributeMaxDynamicSharedMemorySize, smem1);
    cudaFuncSetAttribute(apply_kernel,
                         cudaFuncAttributeMaxDynamicSharedMemorySize, smem3);

    zeroG_kernel<<<(B_ * C_ * C_ + 1023) / 1024, 1024>>>();

    dim3 grid1(72, B_);                   // 72 * 24 chunks * 64 = 110592
    gram_kernel<<<grid1, 256, smem1>>>(x);

    m3_sigmoid_kernel<<<B_, 256>>>();

    dim3 grid3(54, B_);                   // 54 * 32 tiles * 64 = 110592
    apply_kernel<<<grid3, 256, smem3>>>(x, out, gamma);
}

// round 9
// speedup vs baseline: 1.2794x; 1.2794x over previous
#include <cuda_runtime.h>
#include <cstdint>

// Problem constants: x (8, 48, 48, 48, 64) fp32
#define B_   8
#define C_   64
#define N_   110592          // 48*48*48
#define NB_  (C_ * N_)       // 7077888 elements per batch

// Scratch (no allocs allowed): Gram matrix, 8 x 64 x 64 fp32
__device__ float g_G[B_ * C_ * C_];

// ---------------------------------------------------------------------------
// warp mma m16n8k8 tf32: D(16x8,f32) += A(16x8,tf32 row) * B(8x8,tf32 col)
// fragment layout (lane = 4*g + tg, g=lane>>2, tg=lane&3):
//   a0=(g,tg) a1=(g+8,tg) a2=(g,tg+4) a3=(g+8,tg+4)
//   b0=(tg,g) b1=(tg+4,g)
//   c0=(g,2tg) c1=(g,2tg+1) c2=(g+8,2tg) c3=(g+8,2tg+1)
// ---------------------------------------------------------------------------
__device__ __forceinline__ void mma_tf32(
    float& d0, float& d1, float& d2, float& d3,
    uint32_t a0, uint32_t a1, uint32_t a2, uint32_t a3,
    uint32_t b0, uint32_t b1)
{
    asm volatile(
        "mma.sync.aligned.m16n8k8.row.col.f32.tf32.tf32.f32 "
        "{%0,%1,%2,%3}, {%4,%5,%6,%7}, {%8,%9}, {%0,%1,%2,%3};\n"
        : "+f"(d0), "+f"(d1), "+f"(d2), "+f"(d3)
        : "r"(a0), "r"(a1), "r"(a2), "r"(a3), "r"(b0), "r"(b1));
}

__device__ __forceinline__ uint32_t f2u(float f) { return __float_as_uint(f); }

__device__ __forceinline__ uint32_t smem_u32(const void* p) {
    return (uint32_t)__cvta_generic_to_shared(p);
}
// .cg: bypass L1 allocation (streamed data, never re-read through L1)
__device__ __forceinline__ void cp_async16(uint32_t saddr, const void* gptr) {
    asm volatile("cp.async.cg.shared.global [%0], [%1], 16;\n"
                 :: "r"(saddr), "l"(gptr));
}
__device__ __forceinline__ void cp_commit() {
    asm volatile("cp.async.commit_group;\n");
}
template <int N>
__device__ __forceinline__ void cp_wait() {
    asm volatile("cp.async.wait_group %0;\n" :: "n"(N));
}

__device__ __forceinline__ float sigmoidf_(float s) {
    return 1.0f / (1.0f + __expf(-s));
}

// ---------------------------------------------------------------------------
// Kernel 0: zero the Gram accumulator
// ---------------------------------------------------------------------------
__global__ void zeroG_kernel() {
    int i = blockIdx.x * blockDim.x + threadIdx.x;
    if (i < B_ * C_ * C_) g_G[i] = 0.0f;
}

// ---------------------------------------------------------------------------
// Kernel 1: G[b] += K[b] * K[b]^T   (partial Gram per CTA, REDG merge)
// grid (72, 8), block 256, 4 CTAs/SM. 24 chunks of 64 cols, 3-stage pipeline,
// ONE __syncthreads per chunk, prefetch at END of body:
//   wait<1>; sync; compute(ch); prefetch(ch+2); commit
// Safety: prefetch target (ch+2)%3 == (ch-1)%3 was last read in compute(ch-1),
// finished by every warp before the sync this warp passed at top of ch.
// smem: 3 x [64][68] fp32 (68 == 4 mod 32 -> frag reads conflict-free).
// ---------------------------------------------------------------------------
#define S1 68
#define G_CHUNKS 24
__global__ __launch_bounds__(256, 4)
void gram_kernel(const float* __restrict__ x)
{
    extern __shared__ float Ks[];   // 3 * 64 * 68 floats = 52224 B

    const int b    = blockIdx.y;
    const int tid  = threadIdx.x;
    const int warp = tid >> 5;
    const int lane = tid & 31;
    const int g    = lane >> 2;
    const int tg   = lane & 3;
    const int c0   = (warp >> 1) * 16;   // c-block (16 rows)
    const int d0b  = (warp & 1) * 32;    // d-half (32 cols)

    const float* xb   = x + (size_t)b * NB_;
    const int   nbase = blockIdx.x * (G_CHUNKS * 64);

    const int lrow = tid >> 4;           // rows tid/16, +16, +32, +48
    const int lc4  = (tid & 15) << 2;

    float acc[4][4];
#pragma unroll
    for (int i = 0; i < 4; i++)
#pragma unroll
        for (int j = 0; j < 4; j++) acc[i][j] = 0.0f;

    // prologue: prefetch chunks 0 and 1
#pragma unroll
    for (int pf = 0; pf < 2; pf++) {
        const float* gsrc = xb + nbase + pf * 64;
        float* buf = Ks + pf * (64 * S1);
#pragma unroll
        for (int it = 0; it < 4; it++) {
            int row = lrow + it * 16;
            cp_async16(smem_u32(&buf[row * S1 + lc4]),
                       gsrc + (size_t)row * N_ + lc4);
        }
        cp_commit();
    }

    for (int ch = 0; ch < G_CHUNKS; ch++) {
        cp_wait<1>();          // chunk ch resident
        __syncthreads();

        const float* buf = Ks + (ch % 3) * (64 * S1);
#pragma unroll
        for (int ks = 0; ks < 8; ks++) {
            const int kk = ks * 8;
            uint32_t a0 = f2u(buf[(c0 + g)     * S1 + kk + tg]);
            uint32_t a1 = f2u(buf[(c0 + 8 + g) * S1 + kk + tg]);
            uint32_t a2 = f2u(buf[(c0 + g)     * S1 + kk + tg + 4]);
            uint32_t a3 = f2u(buf[(c0 + 8 + g) * S1 + kk + tg + 4]);
#pragma unroll
            for (int db = 0; db < 4; db++) {
                int dr = d0b + db * 8 + g;
                uint32_t b0 = f2u(buf[dr * S1 + kk + tg]);
                uint32_t b1 = f2u(buf[dr * S1 + kk + tg + 4]);
                mma_tf32(acc[db][0], acc[db][1], acc[db][2], acc[db][3],
                         a0, a1, a2, a3, b0, b1);
            }
        }

        // prefetch chunk ch+2 (off the critical compute-entry path)
        if (ch + 2 < G_CHUNKS) {
            const float* gsrc = xb + nbase + (ch + 2) * 64;
            float* pbuf = Ks + ((ch + 2) % 3) * (64 * S1);
#pragma unroll
            for (int it = 0; it < 4; it++) {
                int row = lrow + it * 16;
                cp_async16(smem_u32(&pbuf[row * S1 + lc4]),
                           gsrc + (size_t)row * N_ + lc4);
            }
        }
        cp_commit();           // always commit -> uniform wait counting
    }

    // merge partials: each accumulator value maps to a distinct G entry
    float* Gb = g_G + b * (C_ * C_);
#pragma unroll
    for (int db = 0; db < 4; db++) {
        int d = d0b + db * 8 + tg * 2;
        atomicAdd(&Gb[(c0 + g)     * C_ + d],     acc[db][0]);
        atomicAdd(&Gb[(c0 + g)     * C_ + d + 1], acc[db][1]);
        atomicAdd(&Gb[(c0 + 8 + g) * C_ + d],     acc[db][2]);
        atomicAdd(&Gb[(c0 + 8 + g) * C_ + d + 1], acc[db][3]);
    }
}

// ---------------------------------------------------------------------------
// Kernel 2: out = x + gamma * (sigmoid(G@G) @ K)    [m3+sigmoid FUSED]
// grid (54, 8), block 256, 3 CTAs/SM. Prologue: prefetch tiles 0,1 into
// buffers 0,1; meanwhile compute affinity = sigmoid(G*G) via tf32 mma in
// buffer 2's region (G and affinity both [64][68] <= 64*72 floats), extract
// affinity fragments to registers. Buffer 2 is first written by the tile-2
// prefetch at the END of iteration 0, i.e. after the top-of-loop sync that
// every warp reaches only after finishing the affinity phase -> safe.
// Main loop: ONE sync per tile, prefetch at end of body (same proof as gram).
// smem: 3 x Ks[64][72] (72 == 8 mod 32 -> B-frag banks 8tg+g conflict-free).
// ---------------------------------------------------------------------------
#define S3 72
#define SA 68
#define A_TILES 32
__global__ __launch_bounds__(256, 3)
void apply_kernel(const float* __restrict__ x, float* __restrict__ out,
                  const float* __restrict__ gammap)
{
    extern __shared__ float Ks[];        // 3 * 64 * 72 floats = 55296 B
    float* GA = Ks + 2 * (64 * S3);      // G / affinity region, [64][SA]

    const int b    = blockIdx.y;
    const int tid  = threadIdx.x;
    const int warp = tid >> 5;
    const int lane = tid & 31;
    const int g    = lane >> 2;
    const int tg   = lane & 3;
    const int c0   = (warp >> 1) * 16;   // c-block (16 rows)
    const int nc0  = (warp & 1) * 32;    // n-half (32 cols)

    const float gamma = gammap[0];
    const float* xb   = x + (size_t)b * NB_;
    float*       ob   = out + (size_t)b * NB_;
    const int   nbase = blockIdx.x * (A_TILES * 64);

    const int lrow = tid >> 4;
    const int lc4  = (tid & 15) << 2;

    // prologue: prefetch tiles 0 and 1 (overlaps with affinity phase below)
#pragma unroll
    for (int pf = 0; pf < 2; pf++) {
        const float* gsrc = xb + nbase + pf * 64;
        float* buf = Ks + pf * (64 * S3);
#pragma unroll
        for (int it = 0; it < 4; it++) {
            int row = lrow + it * 16;
            cp_async16(smem_u32(&buf[row * S3 + lc4]),
                       gsrc + (size_t)row * N_ + lc4);
        }
        cp_commit();
    }

    // ---- fused affinity = sigmoid(G @ G) ----
    // load G[b] into GA (stride SA: banks 4*row + col, conflict-free frags)
    for (int i = tid; i < C_ * C_; i += 256)
        GA[(i >> 6) * SA + (i & 63)] = g_G[b * C_ * C_ + i];
    __syncthreads();

    {
        float mac[4][4];
#pragma unroll
        for (int i = 0; i < 4; i++)
#pragma unroll
            for (int j = 0; j < 4; j++) mac[i][j] = 0.0f;

#pragma unroll
        for (int kd = 0; kd < 8; kd++) {
            const int d0 = kd * 8;
            uint32_t a0 = f2u(GA[(c0 + g)     * SA + d0 + tg]);
            uint32_t a1 = f2u(GA[(c0 + 8 + g) * SA + d0 + tg]);
            uint32_t a2 = f2u(GA[(c0 + g)     * SA + d0 + tg + 4]);
            uint32_t a3 = f2u(GA[(c0 + 8 + g) * SA + d0 + tg + 4]);
#pragma unroll
            for (int nb = 0; nb < 4; nb++) {
                const int col = nc0 + nb * 8;
                uint32_t b0 = f2u(GA[(d0 + tg)     * SA + col + g]);
                uint32_t b1 = f2u(GA[(d0 + tg + 4) * SA + col + g]);
                mma_tf32(mac[nb][0], mac[nb][1], mac[nb][2], mac[nb][3],
                         a0, a1, a2, a3, b0, b1);
            }
        }
        __syncthreads();   // all reads of G done before overwrite with affinity

#pragma unroll
        for (int nb = 0; nb < 4; nb++) {
            const int col = nc0 + nb * 8 + 2 * tg;
            GA[(c0 + g)     * SA + col]     = sigmoidf_(mac[nb][0]);
            GA[(c0 + g)     * SA + col + 1] = sigmoidf_(mac[nb][1]);
            GA[(c0 + 8 + g) * SA + col]     = sigmoidf_(mac[nb][2]);
            GA[(c0 + 8 + g) * SA + col + 1] = sigmoidf_(mac[nb][3]);
        }
    }
    __syncthreads();

    // hoist affinity fragments to registers (tile-invariant). 32 regs.
    uint32_t af[8][4];
#pragma unroll
    for (int kd = 0; kd < 8; kd++) {
        const int d0 = kd * 8;
        af[kd][0] = f2u(GA[(c0 + g)     * SA + d0 + tg]);
        af[kd][1] = f2u(GA[(c0 + 8 + g) * SA + d0 + tg]);
        af[kd][2] = f2u(GA[(c0 + g)     * SA + d0 + tg + 4]);
        af[kd][3] = f2u(GA[(c0 + 8 + g) * SA + d0 + tg + 4]);
    }

    // ---- main loop: one sync per tile ----
    for (int t = 0; t < A_TILES; t++) {
        cp_wait<1>();              // tile t resident
        __syncthreads();

        const float* buf = Ks + (t % 3) * (64 * S3);

        float acc[4][4];
#pragma unroll
        for (int i = 0; i < 4; i++)
#pragma unroll
            for (int j = 0; j < 4; j++) acc[i][j] = 0.0f;

#pragma unroll
        for (int kd = 0; kd < 8; kd++) {
            const int d0 = kd * 8;
#pragma unroll
            for (int nb = 0; nb < 4; nb++) {
                const int col = nc0 + nb * 8;
                uint32_t b0 = f2u(buf[(d0 + tg)     * S3 + col + g]);
                uint32_t b1 = f2u(buf[(d0 + tg + 4) * S3 + col + g]);
                mma_tf32(acc[nb][0], acc[nb][1], acc[nb][2], acc[nb][3],
                         af[kd][0], af[kd][1], af[kd][2], af[kd][3], b0, b1);
            }
        }

        // epilogue: out = x + gamma * weights (x re-read from smem tile)
        const int n0 = nbase + t * 64;
#pragma unroll
        for (int nb = 0; nb < 4; nb++) {
            const int col = nc0 + nb * 8 + tg * 2;
            const int r0 = c0 + g;
            const int r1 = c0 + 8 + g;
            float2 x0 = *(const float2*)&buf[r0 * S3 + col];
            float2 x1 = *(const float2*)&buf[r1 * S3 + col];
            float2 o0 = make_float2(fmaf(gamma, acc[nb][0], x0.x),
                                    fmaf(gamma, acc[nb][1], x0.y));
            float2 o1 = make_float2(fmaf(gamma, acc[nb][2], x1.x),
                                    fmaf(gamma, acc[nb][3], x1.y));
            *(float2*)(ob + (size_t)r0 * N_ + n0 + col) = o0;
            *(float2*)(ob + (size_t)r1 * N_ + n0 + col) = o1;
        }

        // prefetch tile t+2 (off the critical compute-entry path)
        if (t + 2 < A_TILES) {
            const float* gsrc = xb + nbase + (t + 2) * 64;
            float* pbuf = Ks + ((t + 2) % 3) * (64 * S3);
#pragma unroll
            for (int it = 0; it < 4; it++) {
                int row = lrow + it * 16;
                cp_async16(smem_u32(&pbuf[row * S3 + lc4]),
                           gsrc + (size_t)row * N_ + lc4);
            }
        }
        cp_commit();               // always commit -> uniform wait counting
    }
}

// ---------------------------------------------------------------------------
// Launch
// ---------------------------------------------------------------------------
extern "C" void kernel_launch(void* const* d_in, const int* in_sizes, int n_in,
                              void* d_out, int out_size)
{
    const float* x     = (const float*)d_in[0];
    const float* gamma = (const float*)d_in[1];
    float*       out   = (float*)d_out;

    (void)in_sizes; (void)n_in; (void)out_size;

    const int smem1 = 3 * 64 * S1 * (int)sizeof(float);   // 52224
    const int smem3 = 3 * 64 * S3 * (int)sizeof(float);   // 55296

    cudaFuncSetAttribute(gram_kernel,
                         cudaFuncAttributeMaxDynamicSharedMemorySize, smem1);
    cudaFuncSetAttribute(apply_kernel,
                         cudaFuncAttributeMaxDynamicSharedMemorySize, smem3);

    zeroG_kernel<<<(B_ * C_ * C_ + 1023) / 1024, 1024>>>();

    dim3 grid1(72, B_);                   // 72 * 24 chunks * 64 = 110592
    gram_kernel<<<grid1, 256, smem1>>>(x);

    dim3 grid3(54, B_);                   // 54 * 32 tiles * 64 = 110592
    apply_kernel<<<grid3, 256, smem3>>>(x, out, gamma);
}